// round 7
// baseline (speedup 1.0000x reference)
#include <cuda_runtime.h>
#include <cuda_fp16.h>
#include <cstdint>
#include <cstddef>

#define LOG2E 1.4426950408889634f
#define LN2f  0.6931471805599453f
#define NEGV  -100.0f
#define SBITS 20.0f        // emission table pre-scale = 2^20
#define SINT  20

#define T_LEN 1024
#define V_N   8000
#define TPB   256
#define WPB   8            // warps (=sequences) per block
#define PITCH 33

// -------- device scratch (static allocation only) ---------------------------
__device__ __align__(8) ushort4 g_Bh4[V_N];  // fp16 emission probs * 2^20, [y].{s0..s3}
__device__ float g_par[16];  // [0..3] pi_log2, [4..7] pi_prob, [8..11] A0p, [12..15] A1p

// ---------------------------- prep kernel -----------------------------------
__global__ void prep_kernel(const float* __restrict__ init_pi,
                            const float* __restrict__ init_A,
                            const float* __restrict__ init_B) {
    __shared__ float red[256];
    int tid = threadIdx.x;
    int s = blockIdx.x;
    if (s < 4) {
        const float* row = init_B + (size_t)s * V_N;
        float mx = -1e30f;
        for (int i = tid; i < V_N; i += 256) mx = fmaxf(mx, row[i]);
        red[tid] = mx; __syncthreads();
        for (int o = 128; o; o >>= 1) {
            if (tid < o) red[tid] = fmaxf(red[tid], red[tid + o]);
            __syncthreads();
        }
        mx = red[0]; __syncthreads();
        float sm = 0.f;
        for (int i = tid; i < V_N; i += 256) sm += expf(row[i] - mx);
        red[tid] = sm; __syncthreads();
        for (int o = 128; o; o >>= 1) {
            if (tid < o) red[tid] += red[tid + o];
            __syncthreads();
        }
        float lse = mx + logf(red[0]);
        for (int i = tid; i < V_N; i += 256) {
            float lb2 = fmaxf(row[i] - lse, NEGV) * LOG2E;   // log2 emission
            float pv  = exp2f(lb2 + SBITS);                  // scaled prob, fp16-safe range
            ((unsigned short*)&g_Bh4[i])[s] = __half_as_ushort(__float2half_rn(pv));
        }
    } else if (tid == 0) {
        float x[4];
        const float pim[4] = {0.f, NEGV, NEGV, 0.f};
        float mx = -1e30f;
        for (int i = 0; i < 4; ++i) { x[i] = init_pi[i] + pim[i]; mx = fmaxf(mx, x[i]); }
        float smv = 0.f;
        for (int i = 0; i < 4; ++i) smv += expf(x[i] - mx);
        float lse = mx + logf(smv);
        for (int i = 0; i < 4; ++i) {
            float pl = fmaxf(x[i] - lse, NEGV) * LOG2E;
            g_par[i] = pl;
            g_par[4 + i] = exp2f(pl);
        }
        const int pat[16] = {0,1,1,0, 0,1,1,0, 1,0,0,1, 1,0,0,1};
        float Ap[16];
        for (int r = 0; r < 4; ++r) {
            float y[4]; float m2 = -1e30f;
            for (int j = 0; j < 4; ++j) {
                y[j] = init_A[r * 4 + j] + (pat[r * 4 + j] ? 0.f : NEGV);
                m2 = fmaxf(m2, y[j]);
            }
            float s2 = 0.f;
            for (int j = 0; j < 4; ++j) s2 += expf(y[j] - m2);
            float l2 = m2 + logf(s2);
            for (int j = 0; j < 4; ++j)
                Ap[r * 4 + j] = expf(fmaxf(y[j] - l2, NEGV));
        }
        // col s allowed preds: s0<-{2,3}, s1<-{0,1}, s2<-{0,1}, s3<-{2,3}
        g_par[8]  = Ap[2*4+0]; g_par[12] = Ap[3*4+0];
        g_par[9]  = Ap[0*4+1]; g_par[13] = Ap[1*4+1];
        g_par[10] = Ap[0*4+2]; g_par[14] = Ap[1*4+2];
        g_par[11] = Ap[2*4+3]; g_par[15] = Ap[3*4+3];
    }
}

// ---------------------------- main kernel -----------------------------------
__device__ __forceinline__ float flg2(float x) {
    float r; asm("lg2.approx.ftz.f32 %0, %1;" : "=f"(r) : "f"(x)); return r;
}

__device__ __forceinline__ float4 emis(const uint2* __restrict__ bt, int y) {
    uint2 u = bt[y];
    float2 f0 = __half22float2(*reinterpret_cast<__half2*>(&u.x));
    float2 f1 = __half22float2(*reinterpret_cast<__half2*>(&u.y));
    return make_float4(f0.x, f0.y, f1.x, f1.y);
}

__device__ __forceinline__ void rescale16(float* p, int& E) {
    float mx = p[0];
#pragma unroll
    for (int k = 1; k < 16; ++k) mx = fmaxf(mx, p[k]);
    int ex = (int)((__float_as_uint(mx) >> 23) & 255u) - 127;
    float sc = __uint_as_float((unsigned)(127 - ex) << 23);
#pragma unroll
    for (int k = 0; k < 16; ++k) p[k] *= sc;
    E += ex;
}

// smem offsets (bytes)
#define OFF_BT 0
#define OFF_YT (V_N * 8)                          // 64,000
#define OFF_MS (OFF_YT + WPB * 32 * PITCH * 4)    // 64,000 + 33,792 = 97,792
#define SMEMSZ (OFF_MS + WPB * 256 * 4)           // 105,984

__global__ void __launch_bounds__(TPB, 2)
hmm_kernel(const int* __restrict__ Y, const float* __restrict__ mask,
           float* __restrict__ out) {
    extern __shared__ __align__(16) char raw[];
    uint2*    bt   = reinterpret_cast<uint2*>(raw + OFF_BT);
    int*      ytA  = reinterpret_cast<int*>(raw + OFF_YT);
    unsigned* msA  = reinterpret_cast<unsigned*>(raw + OFF_MS);

    const int tid = threadIdx.x, w = tid >> 5, lane = tid & 31;
    int*      ytw = ytA + w * (32 * PITCH);
    unsigned* msw = msA + w * 256;

    // ---- stage fp16 emission table (coalesced, L2-resident after prep) ----
    {
        const uint2* src = reinterpret_cast<const uint2*>(g_Bh4);
        for (int i = tid; i < V_N; i += TPB) bt[i] = src[i];
    }

    // ---- stage my warp's sequence: coalesced LDG -> padded tile / bit words ----
    const int seq = blockIdx.x * WPB + w;
    {
        const int4*   y4 = (const int4*)(Y    + (size_t)seq * T_LEN);
        const float4* m4 = (const float4*)(mask + (size_t)seq * T_LEN);
#pragma unroll
        for (int m = 0; m < 8; ++m) {
            int4   yv = y4[m * 32 + lane];
            float4 mv = m4[m * 32 + lane];
            int t = m * 128 + lane * 4;
            int a = (t >> 5) * PITCH + (t & 31);
            ytw[a] = yv.x; ytw[a+1] = yv.y; ytw[a+2] = yv.z; ytw[a+3] = yv.w;
            unsigned pb = (mv.x > 0.5f ? 1u : 0u) | (mv.y > 0.5f ? 0x100u : 0u)
                        | (mv.z > 0.5f ? 0x10000u : 0u) | (mv.w > 0.5f ? 0x1000000u : 0u);
            msw[m * 32 + lane] = pb;
        }
    }
    __syncthreads();

    // ---- per-lane mask bitmask: bit j = mask[lane*32 + j] ----
    unsigned mbits = 0;
#pragma unroll
    for (int k = 0; k < 8; ++k) {
        unsigned pw = msw[lane * 8 + k];
        mbits |= ((pw & 1u)           << (4 * k))
               | (((pw >> 8)  & 1u)  << (4 * k + 1))
               | (((pw >> 16) & 1u)  << (4 * k + 2))
               | (((pw >> 24) & 1u)  << (4 * k + 3));
    }
    if (lane == 0) mbits &= ~1u;      // t=0 lives in alpha0, never a transition

    const float pl0 = g_par[0],  pl1 = g_par[1],  pl2 = g_par[2],  pl3 = g_par[3];
    const float pp0 = g_par[4],  pp1 = g_par[5],  pp2 = g_par[6],  pp3 = g_par[7];
    const float B00 = g_par[8],  B01 = g_par[9],  B02 = g_par[10], B03 = g_par[11];
    const float B10 = g_par[12], B11 = g_par[13], B12 = g_par[14], B13 = g_par[15];
    const int base = lane * PITCH;

    // ================= pass 1: chunk transfer matrix =================
    float p[16];
#pragma unroll
    for (int k = 0; k < 16; ++k) p[k] = (k % 5 == 0) ? 1.f : 0.f;   // identity
    int E = 0;

    {
        int    yv = ytw[base];
        float4 e  = emis(bt, yv);
#pragma unroll
        for (int j = 0; j < 32; ++j) {
            float4 ec = e;
            if (j < 31) {                      // prefetch next (off the p-chain)
                int yn = ytw[base + j + 1];
                e = emis(bt, yn);
            }
            bool mk = (mbits >> j) & 1u;
            float c00 = B00*ec.x, c10 = B10*ec.x;
            float c01 = B01*ec.y, c11 = B11*ec.y;
            float c02 = B02*ec.z, c12 = B12*ec.z;
            float c03 = B03*ec.w, c13 = B13*ec.w;
            float n[16];
#pragma unroll
            for (int r = 0; r < 4; ++r) {
                float a0 = p[r*4+0], a1 = p[r*4+1], a2 = p[r*4+2], a3 = p[r*4+3];
                n[r*4+0] = fmaf(a3, c10, a2 * c00);
                n[r*4+1] = fmaf(a1, c11, a0 * c01);
                n[r*4+2] = fmaf(a1, c12, a0 * c02);
                n[r*4+3] = fmaf(a3, c13, a2 * c03);
            }
#pragma unroll
            for (int k = 0; k < 16; ++k) p[k] = mk ? n[k] : p[k];
            if ((j & 7) == 7) rescale16(p, E);
        }
        E -= SINT * __popc(mbits);            // exponent shift: one per unmasked step
    }

    // ================= pass 2: Kogge-Stone inclusive scan =================
#pragma unroll
    for (int d = 1; d < 32; d <<= 1) {
        float q[16];
#pragma unroll
        for (int k = 0; k < 16; ++k) q[k] = __shfl_up_sync(0xffffffffu, p[k], d);
        int Eq = __shfl_up_sync(0xffffffffu, E, d);
        if (lane >= d) {
            float n[16];
#pragma unroll
            for (int r = 0; r < 4; ++r)
#pragma unroll
                for (int s = 0; s < 4; ++s)
                    n[r*4+s] = fmaf(q[r*4+3], p[12+s],
                               fmaf(q[r*4+2], p[8+s],
                               fmaf(q[r*4+1], p[4+s], q[r*4+0] * p[s])));
#pragma unroll
            for (int k = 0; k < 16; ++k) p[k] = n[k];
            E += Eq;
        }
        rescale16(p, E);          // unconditional renorm, valid for all lanes
    }
    // exclusive shift: H_i = G_0 .. G_{i-1}
    float h[16]; int Eh;
#pragma unroll
    for (int k = 0; k < 16; ++k) h[k] = __shfl_up_sync(0xffffffffu, p[k], 1);
    Eh = __shfl_up_sync(0xffffffffu, E, 1);
    if (lane == 0) {
#pragma unroll
        for (int k = 0; k < 16; ++k) h[k] = (k % 5 == 0) ? 1.f : 0.f;
        Eh = 0;
    }

    // ---- starting alpha for my chunk: A_i = alpha0 · H_i ----
    int    y0 = ytw[0];                       // broadcast LDS
    float4 e0 = emis(bt, y0);
    float a00 = pp0 * e0.x, a01 = pp1 * e0.y, a02 = pp2 * e0.z, a03 = pp3 * e0.w;
    float al0 = fmaf(a03, h[12+0], fmaf(a02, h[8+0], fmaf(a01, h[4+0], a00 * h[0])));
    float al1 = fmaf(a03, h[12+1], fmaf(a02, h[8+1], fmaf(a01, h[4+1], a00 * h[1])));
    float al2 = fmaf(a03, h[12+2], fmaf(a02, h[8+2], fmaf(a01, h[4+2], a00 * h[2])));
    float al3 = fmaf(a03, h[12+3], fmaf(a02, h[8+3], fmaf(a01, h[4+3], a00 * h[3])));
    E = Eh - SINT;
    {
        float mx = fmaxf(fmaxf(al0, al1), fmaxf(al2, al3));
        int ex = (int)((__float_as_uint(mx) >> 23) & 255u) - 127;
        float sc = __uint_as_float((unsigned)(127 - ex) << 23);
        al0 *= sc; al1 *= sc; al2 *= sc; al3 *= sc; E += ex;
    }

    // ================= pass 3: replay chunk, emit log outputs =================
    float* o0 = out + (size_t)(seq * 4 + 0) * T_LEN + lane * 32;
    float* o1 = out + (size_t)(seq * 4 + 1) * T_LEN + lane * 32;
    float* o2 = out + (size_t)(seq * 4 + 2) * T_LEN + lane * 32;
    float* o3 = out + (size_t)(seq * 4 + 3) * T_LEN + lane * 32;

    int    yv = ytw[base];
    float4 e  = emis(bt, yv);
#pragma unroll
    for (int jo = 0; jo < 4; ++jo) {
        float b0[8], b1[8], b2[8], b3[8];
#pragma unroll
        for (int ji = 0; ji < 8; ++ji) {
            const int j = jo * 8 + ji;
            float4 ec = e;
            if (j < 31) {
                int yn = ytw[base + j + 1];
                e = emis(bt, yn);
            }
            bool mk = (mbits >> j) & 1u;
            float c00 = B00*ec.x, c10 = B10*ec.x;
            float c01 = B01*ec.y, c11 = B11*ec.y;
            float c02 = B02*ec.z, c12 = B12*ec.z;
            float c03 = B03*ec.w, c13 = B13*ec.w;
            float n0 = fmaf(al3, c10, al2 * c00);
            float n1 = fmaf(al1, c11, al0 * c01);
            float n2 = fmaf(al1, c12, al0 * c02);
            float n3 = fmaf(al3, c13, al2 * c03);
            al0 = mk ? n0 : al0;  al1 = mk ? n1 : al1;
            al2 = mk ? n2 : al2;  al3 = mk ? n3 : al3;
            E = mk ? E - SINT : E;
            float EfL = (float)E * LN2f;
            b0[ji] = fmaf(flg2(al0), LN2f, EfL);
            b1[ji] = fmaf(flg2(al1), LN2f, EfL);
            b2[ji] = fmaf(flg2(al2), LN2f, EfL);
            b3[ji] = fmaf(flg2(al3), LN2f, EfL);
            if (jo == 0 && ji == 0 && lane == 0) {
                // exact t=0 (pi-masked states underflow in prob domain)
                b0[0] = (pl0 + flg2(e0.x) - SBITS) * LN2f;
                b1[0] = (pl1 + flg2(e0.y) - SBITS) * LN2f;
                b2[0] = (pl2 + flg2(e0.z) - SBITS) * LN2f;
                b3[0] = (pl3 + flg2(e0.w) - SBITS) * LN2f;
            }
        }
        int t8 = jo * 8;
        *(float4*)(o0 + t8)     = make_float4(b0[0], b0[1], b0[2], b0[3]);
        *(float4*)(o0 + t8 + 4) = make_float4(b0[4], b0[5], b0[6], b0[7]);
        *(float4*)(o1 + t8)     = make_float4(b1[0], b1[1], b1[2], b1[3]);
        *(float4*)(o1 + t8 + 4) = make_float4(b1[4], b1[5], b1[6], b1[7]);
        *(float4*)(o2 + t8)     = make_float4(b2[0], b2[1], b2[2], b2[3]);
        *(float4*)(o2 + t8 + 4) = make_float4(b2[4], b2[5], b2[6], b2[7]);
        *(float4*)(o3 + t8)     = make_float4(b3[0], b3[1], b3[2], b3[3]);
        *(float4*)(o3 + t8 + 4) = make_float4(b3[4], b3[5], b3[6], b3[7]);
        {
            float mx = fmaxf(fmaxf(al0, al1), fmaxf(al2, al3));
            int ex = (int)((__float_as_uint(mx) >> 23) & 255u) - 127;
            float sc = __uint_as_float((unsigned)(127 - ex) << 23);
            al0 *= sc; al1 *= sc; al2 *= sc; al3 *= sc; E += ex;
        }
    }
}

// ---------------------------- launch ----------------------------------------
extern "C" void kernel_launch(void* const* d_in, const int* in_sizes, int n_in,
                              void* d_out, int out_size) {
    const int*   Y    = (const int*)d_in[0];
    const float* mask = (const float*)d_in[1];
    const float* pi   = (const float*)d_in[2];
    const float* A    = (const float*)d_in[3];
    const float* B    = (const float*)d_in[4];
    float* out = (float*)d_out;

    int N = in_sizes[0] / T_LEN;          // 8192

    cudaFuncSetAttribute(hmm_kernel,
                         cudaFuncAttributeMaxDynamicSharedMemorySize, SMEMSZ);

    prep_kernel<<<5, 256>>>(pi, A, B);
    hmm_kernel<<<N / WPB, TPB, SMEMSZ>>>(Y, mask, out);
}

// round 10
// speedup vs baseline: 1.6092x; 1.6092x over previous
#include <cuda_runtime.h>
#include <cuda_fp16.h>
#include <cstdint>
#include <cstddef>

#define LOG2E 1.4426950408889634f
#define LN2f  0.6931471805599453f
#define NEGV  -100.0f
#define SBITS 20.0f        // emission table pre-scale = 2^20
#define SINT  20

#define T_LEN 1024
#define V_N   8000
#define TPB   256
#define WPB   8            // warps (=sequences) per block

// smem layout (bytes)
#define OFF_BT 0
#define OS_WST (8 * 36)                           // floats per (warp,state) quarter-tile
#define OFF_OS (V_N * 8)                          // 64,000
#define SMEMSZ (OFF_OS + WPB * 4 * OS_WST * 4)    // 64,000 + 36,864 = 100,864 B

// -------- device scratch (static allocation only) ---------------------------
__device__ __align__(8) ushort4 g_Bh4[V_N];  // fp16 emission probs * 2^20, [y].{s0..s3}
__device__ float g_par[16];  // [0..3] pi_log2, [4..7] pi_prob, [8..11] A0p, [12..15] A1p

// ---------------------------- prep kernel -----------------------------------
__global__ void prep_kernel(const float* __restrict__ init_pi,
                            const float* __restrict__ init_A,
                            const float* __restrict__ init_B) {
    __shared__ float red[256];
    int tid = threadIdx.x;
    int s = blockIdx.x;
    if (s < 4) {
        const float* row = init_B + (size_t)s * V_N;
        float mx = -1e30f;
        for (int i = tid; i < V_N; i += 256) mx = fmaxf(mx, row[i]);
        red[tid] = mx; __syncthreads();
        for (int o = 128; o; o >>= 1) {
            if (tid < o) red[tid] = fmaxf(red[tid], red[tid + o]);
            __syncthreads();
        }
        mx = red[0]; __syncthreads();
        float sm = 0.f;
        for (int i = tid; i < V_N; i += 256) sm += expf(row[i] - mx);
        red[tid] = sm; __syncthreads();
        for (int o = 128; o; o >>= 1) {
            if (tid < o) red[tid] += red[tid + o];
            __syncthreads();
        }
        float lse = mx + logf(red[0]);
        for (int i = tid; i < V_N; i += 256) {
            float lb2 = fmaxf(row[i] - lse, NEGV) * LOG2E;   // log2 emission
            float pv  = exp2f(lb2 + SBITS);                  // scaled prob, fp16-safe
            ((unsigned short*)&g_Bh4[i])[s] = __half_as_ushort(__float2half_rn(pv));
        }
    } else if (tid == 0) {
        float x[4];
        const float pim[4] = {0.f, NEGV, NEGV, 0.f};
        float mx = -1e30f;
        for (int i = 0; i < 4; ++i) { x[i] = init_pi[i] + pim[i]; mx = fmaxf(mx, x[i]); }
        float smv = 0.f;
        for (int i = 0; i < 4; ++i) smv += expf(x[i] - mx);
        float lse = mx + logf(smv);
        for (int i = 0; i < 4; ++i) {
            float pl = fmaxf(x[i] - lse, NEGV) * LOG2E;
            g_par[i] = pl;
            g_par[4 + i] = exp2f(pl);
        }
        const int pat[16] = {0,1,1,0, 0,1,1,0, 1,0,0,1, 1,0,0,1};
        float Ap[16];
        for (int r = 0; r < 4; ++r) {
            float y[4]; float m2 = -1e30f;
            for (int j = 0; j < 4; ++j) {
                y[j] = init_A[r * 4 + j] + (pat[r * 4 + j] ? 0.f : NEGV);
                m2 = fmaxf(m2, y[j]);
            }
            float s2 = 0.f;
            for (int j = 0; j < 4; ++j) s2 += expf(y[j] - m2);
            float l2 = m2 + logf(s2);
            for (int j = 0; j < 4; ++j)
                Ap[r * 4 + j] = expf(fmaxf(y[j] - l2, NEGV));
        }
        // col s allowed preds: s0<-{2,3}, s1<-{0,1}, s2<-{0,1}, s3<-{2,3}
        g_par[8]  = Ap[2*4+0]; g_par[12] = Ap[3*4+0];
        g_par[9]  = Ap[0*4+1]; g_par[13] = Ap[1*4+1];
        g_par[10] = Ap[0*4+2]; g_par[14] = Ap[1*4+2];
        g_par[11] = Ap[2*4+3]; g_par[15] = Ap[3*4+3];
    }
}

// ---------------------------- main kernel -----------------------------------
__device__ __forceinline__ float flg2(float x) {
    float r; asm("lg2.approx.ftz.f32 %0, %1;" : "=f"(r) : "f"(x)); return r;
}

__device__ __forceinline__ float4 emis(const uint2* __restrict__ bt, int y) {
    uint2 u = bt[y];
    float2 f0 = __half22float2(*reinterpret_cast<__half2*>(&u.x));
    float2 f1 = __half22float2(*reinterpret_cast<__half2*>(&u.y));
    return make_float4(f0.x, f0.y, f1.x, f1.y);
}

__device__ __forceinline__ void rescale16(float* p, int& E) {
    float mx = p[0];
#pragma unroll
    for (int k = 1; k < 16; ++k) mx = fmaxf(mx, p[k]);
    int ex = (int)((__float_as_uint(mx) >> 23) & 255u) - 127;
    float sc = __uint_as_float((unsigned)(127 - ex) << 23);
#pragma unroll
    for (int k = 0; k < 16; ++k) p[k] *= sc;
    E += ex;
}

__global__ void __launch_bounds__(TPB, 2)
hmm_kernel(const int* __restrict__ Y, const float* __restrict__ mask,
           float* __restrict__ out) {
    extern __shared__ __align__(16) char raw[];
    uint2* bt  = reinterpret_cast<uint2*>(raw + OFF_BT);
    float* osA = reinterpret_cast<float*>(raw + OFF_OS);

    const int tid = threadIdx.x, w = tid >> 5, lane = tid & 31;
    float* osw = osA + w * 4 * OS_WST;

    // ---- stage fp16 emission table (coalesced, L2-resident after prep) ----
    {
        const uint2* src = reinterpret_cast<const uint2*>(g_Bh4);
        for (int i = tid; i < V_N; i += TPB) bt[i] = src[i];
    }
    __syncthreads();

    const int seq = blockIdx.x * WPB + w;

    // ---- load my 32-step segment once: y packed 2/reg, mask -> bitmask ----
    unsigned ypk[16];
    unsigned mbits = 0;
    {
        const int4*   yp = (const int4*)(Y    + (size_t)seq * T_LEN + lane * 32);
        const float4* mp = (const float4*)(mask + (size_t)seq * T_LEN + lane * 32);
#pragma unroll
        for (int g = 0; g < 8; ++g) {
            int4 yv = yp[g];
            ypk[g * 2]     = (unsigned)yv.x | ((unsigned)yv.y << 16);
            ypk[g * 2 + 1] = (unsigned)yv.z | ((unsigned)yv.w << 16);
            float4 mv = mp[g];
            unsigned b = (mv.x > 0.5f ? 1u : 0u) | (mv.y > 0.5f ? 2u : 0u)
                       | (mv.z > 0.5f ? 4u : 0u) | (mv.w > 0.5f ? 8u : 0u);
            mbits |= b << (g * 4);
        }
    }
    if (lane == 0) mbits &= ~1u;      // t=0 lives in alpha0, never a transition

    // transition coefficients (persistent, 8 regs)
    const float B00 = g_par[8],  B01 = g_par[9],  B02 = g_par[10], B03 = g_par[11];
    const float B10 = g_par[12], B11 = g_par[13], B12 = g_par[14], B13 = g_par[15];

    // ================= pass 1: chunk transfer matrix =================
    float p[16];
#pragma unroll
    for (int k = 0; k < 16; ++k) p[k] = (k % 5 == 0) ? 1.f : 0.f;   // identity
    int E = 0;
    {
        float4 e = emis(bt, ypk[0] & 0xFFFFu);
#pragma unroll
        for (int j = 0; j < 32; ++j) {
            float4 ec = e;
            if (j < 31) {                    // prefetch next (off the p-chain)
                int yn = (ypk[(j + 1) >> 1] >> (((j + 1) & 1) * 16)) & 0xFFFF;
                e = emis(bt, yn);
            }
            bool mk = (mbits >> j) & 1u;
            float c00 = B00*ec.x, c10 = B10*ec.x;
            float c01 = B01*ec.y, c11 = B11*ec.y;
            float c02 = B02*ec.z, c12 = B12*ec.z;
            float c03 = B03*ec.w, c13 = B13*ec.w;
            float n[16];
#pragma unroll
            for (int r = 0; r < 4; ++r) {
                float a0 = p[r*4+0], a1 = p[r*4+1], a2 = p[r*4+2], a3 = p[r*4+3];
                n[r*4+0] = fmaf(a3, c10, a2 * c00);
                n[r*4+1] = fmaf(a1, c11, a0 * c01);
                n[r*4+2] = fmaf(a1, c12, a0 * c02);
                n[r*4+3] = fmaf(a3, c13, a2 * c03);
            }
#pragma unroll
            for (int k = 0; k < 16; ++k) p[k] = mk ? n[k] : p[k];
            if ((j & 7) == 7) rescale16(p, E);
        }
        E -= SINT * __popc(mbits);           // exponent shift per unmasked step
    }

    // ================= pass 2: Kogge-Stone inclusive scan =================
#pragma unroll
    for (int d = 1; d < 32; d <<= 1) {
        float q[16];
#pragma unroll
        for (int k = 0; k < 16; ++k) q[k] = __shfl_up_sync(0xffffffffu, p[k], d);
        int Eq = __shfl_up_sync(0xffffffffu, E, d);
        if (lane >= d) {
            float n[16];
#pragma unroll
            for (int r = 0; r < 4; ++r)
#pragma unroll
                for (int s = 0; s < 4; ++s)
                    n[r*4+s] = fmaf(q[r*4+3], p[12+s],
                               fmaf(q[r*4+2], p[8+s],
                               fmaf(q[r*4+1], p[4+s], q[r*4+0] * p[s])));
#pragma unroll
            for (int k = 0; k < 16; ++k) p[k] = n[k];
            E += Eq;
        }
        rescale16(p, E);          // unconditional renorm, valid for all lanes
    }
    // exclusive shift: H_i = G_0 .. G_{i-1} (reuse p as h)
#pragma unroll
    for (int k = 0; k < 16; ++k) p[k] = __shfl_up_sync(0xffffffffu, p[k], 1);
    E = __shfl_up_sync(0xffffffffu, E, 1);
    if (lane == 0) {
#pragma unroll
        for (int k = 0; k < 16; ++k) p[k] = (k % 5 == 0) ? 1.f : 0.f;
        E = 0;
    }

    // ---- starting alpha for my chunk: A_i = alpha0 · H_i ----
    int    y0 = __shfl_sync(0xffffffffu, (int)(ypk[0] & 0xFFFFu), 0);
    float4 e0 = emis(bt, y0);
    float al0, al1, al2, al3;
    {
        float a00 = g_par[4] * e0.x, a01 = g_par[5] * e0.y;   // pi probs loaded here
        float a02 = g_par[6] * e0.z, a03 = g_par[7] * e0.w;
        al0 = fmaf(a03, p[12+0], fmaf(a02, p[8+0], fmaf(a01, p[4+0], a00 * p[0])));
        al1 = fmaf(a03, p[12+1], fmaf(a02, p[8+1], fmaf(a01, p[4+1], a00 * p[1])));
        al2 = fmaf(a03, p[12+2], fmaf(a02, p[8+2], fmaf(a01, p[4+2], a00 * p[2])));
        al3 = fmaf(a03, p[12+3], fmaf(a02, p[8+3], fmaf(a01, p[4+3], a00 * p[3])));
    }
    E -= SINT;
    {
        float mx = fmaxf(fmaxf(al0, al1), fmaxf(al2, al3));
        int ex = (int)((__float_as_uint(mx) >> 23) & 255u) - 127;
        float sc = __uint_as_float((unsigned)(127 - ex) << 23);
        al0 *= sc; al1 *= sc; al2 *= sc; al3 *= sc; E += ex;
    }

    // ==== pass 3: replay in four 8-step quarters, staged coalesced flush ====
    float* os0 = osw + 0 * OS_WST;
    float* os1 = osw + 1 * OS_WST;
    float* os2 = osw + 2 * OS_WST;
    float* os3 = osw + 3 * OS_WST;

    float4 e = emis(bt, ypk[0] & 0xFFFFu);
#pragma unroll
    for (int qt = 0; qt < 4; ++qt) {
#pragma unroll
        for (int u = 0; u < 8; ++u) {
            const int j = qt * 8 + u;
            float4 ec = e;
            if (j < 31) {
                int yn = (ypk[(j + 1) >> 1] >> (((j + 1) & 1) * 16)) & 0xFFFF;
                e = emis(bt, yn);
            }
            bool mk = (mbits >> j) & 1u;
            float c00 = B00*ec.x, c10 = B10*ec.x;
            float c01 = B01*ec.y, c11 = B11*ec.y;
            float c02 = B02*ec.z, c12 = B12*ec.z;
            float c03 = B03*ec.w, c13 = B13*ec.w;
            float n0 = fmaf(al3, c10, al2 * c00);
            float n1 = fmaf(al1, c11, al0 * c01);
            float n2 = fmaf(al1, c12, al0 * c02);
            float n3 = fmaf(al3, c13, al2 * c03);
            al0 = mk ? n0 : al0;  al1 = mk ? n1 : al1;
            al2 = mk ? n2 : al2;  al3 = mk ? n3 : al3;
            E = mk ? E - SINT : E;
            float EfL = (float)E * LN2f;
            float b0 = fmaf(flg2(al0), LN2f, EfL);
            float b1 = fmaf(flg2(al1), LN2f, EfL);
            float b2 = fmaf(flg2(al2), LN2f, EfL);
            float b3 = fmaf(flg2(al3), LN2f, EfL);
            if (qt == 0 && u == 0 && lane == 0) {
                // exact t=0 (pi-masked states underflow in prob domain)
                b0 = (g_par[0] + flg2(e0.x) - SBITS) * LN2f;
                b1 = (g_par[1] + flg2(e0.y) - SBITS) * LN2f;
                b2 = (g_par[2] + flg2(e0.z) - SBITS) * LN2f;
                b3 = (g_par[3] + flg2(e0.w) - SBITS) * LN2f;
            }
            int a = u * 36 + lane;                     // conflict-free STS
            os0[a] = b0;  os1[a] = b1;  os2[a] = b2;  os3[a] = b3;
            if (u == 7) {
                float mx = fmaxf(fmaxf(al0, al1), fmaxf(al2, al3));
                int ex = (int)((__float_as_uint(mx) >> 23) & 255u) - 127;
                float sc = __uint_as_float((unsigned)(127 - ex) << 23);
                al0 *= sc; al1 *= sc; al2 *= sc; al3 *= sc; E += ex;
            }
        }
        __syncwarp();
        // flush quarter: lane (h,r) writes t = col*32 + qt*8 + r, col = i*4+h
        {
            const int r = lane & 7, h = lane >> 3;
#pragma unroll
            for (int s = 0; s < 4; ++s) {
                const float* src = osw + s * OS_WST + r * 36;
                float* dst = out + (size_t)(seq * 4 + s) * T_LEN + qt * 8 + r;
#pragma unroll
                for (int i = 0; i < 8; ++i) {
                    int col = i * 4 + h;
                    dst[col * 32] = src[col];   // LDS conflict-free, STG full sectors
                }
            }
        }
        __syncwarp();
    }
}

// ---------------------------- launch ----------------------------------------
extern "C" void kernel_launch(void* const* d_in, const int* in_sizes, int n_in,
                              void* d_out, int out_size) {
    const int*   Y    = (const int*)d_in[0];
    const float* mask = (const float*)d_in[1];
    const float* pi   = (const float*)d_in[2];
    const float* A    = (const float*)d_in[3];
    const float* B    = (const float*)d_in[4];
    float* out = (float*)d_out;

    int N = in_sizes[0] / T_LEN;          // 8192

    cudaFuncSetAttribute(hmm_kernel,
                         cudaFuncAttributeMaxDynamicSharedMemorySize, SMEMSZ);

    prep_kernel<<<5, 256>>>(pi, A, B);
    hmm_kernel<<<N / WPB, TPB, SMEMSZ>>>(Y, mask, out);
}